// round 2
// baseline (speedup 1.0000x reference)
#include <cuda_runtime.h>
#include <cuda_bf16.h>

#define NN      100000
#define NE      300000
#define HID     256
#define NLAYERS 3
#define BM      64
#define BK      16
#define LN_EPS  1e-5f

// Scratch (static device arrays — allocation-guard-safe)
__device__ float g_agg[NN * HID];
__device__ float g_t  [NN * HID];
__device__ float g_h1 [NN * HID];
__device__ float g_h2 [NN * HID];

// ---------------------------------------------------------------------------
// Edge scatter: agg[dst] += h[src].  64 threads per edge, float4 per thread.
// edge_index dtype (int32 vs int64) detected in-kernel: int64 data viewed as
// int32 has zero high words at odd positions (indices < 2^31).
// ---------------------------------------------------------------------------
__global__ __launch_bounds__(256) void scatter_add_kernel(
    const float* __restrict__ h,
    const void* __restrict__ edge_raw,
    float* __restrict__ agg,
    int n_edges)
{
    int e  = blockIdx.x * 4 + (threadIdx.x >> 6);
    int t  = threadIdx.x & 63;                  // 64 threads -> 256 floats
    if (e >= n_edges) return;

    const int* e32 = (const int*)edge_raw;
    // dtype probe (L1-cached, uniform branch)
    bool is64 = (e32[1] == 0) & (e32[3] == 0) & (e32[5] == 0) & (e32[7] == 0);

    long long s, d;
    if (is64) {
        const long long* e64 = (const long long*)edge_raw;
        s = e64[e];
        d = e64[n_edges + e];
    } else {
        s = e32[e];
        d = e32[n_edges + e];
    }

    float4 v = *reinterpret_cast<const float4*>(h + (size_t)s * HID + t * 4);
    float* o = agg + (size_t)d * HID + t * 4;
#if __CUDA_ARCH__ >= 900
    atomicAdd(reinterpret_cast<float4*>(o), v);
#else
    atomicAdd(o + 0, v.x);
    atomicAdd(o + 1, v.y);
    atomicAdd(o + 2, v.z);
    atomicAdd(o + 3, v.w);
#endif
}

// ---------------------------------------------------------------------------
// GEMM1 (fused z): t = relu( ((1+eps)*h + agg) @ W1 + b1 )
// Block tile 64x256 (full hidden width), BK=16, 256 threads, 8x8 per thread.
// ---------------------------------------------------------------------------
__global__ __launch_bounds__(256) void gin_mlp1_kernel(
    const float* __restrict__ h,
    const float* __restrict__ agg,
    const float* __restrict__ W,
    const float* __restrict__ b,
    const float* __restrict__ eps,
    int layer,
    float* __restrict__ out,
    int n)
{
    __shared__ float As[BK][BM + 1];
    __shared__ float Bs[BK][HID];

    const float c1 = 1.0f + eps[layer];
    const int tid = threadIdx.x;
    const int tx  = tid & 31;
    const int ty  = tid >> 5;
    const int bm0 = blockIdx.x * BM;

    const int arow = tid >> 2;          // 0..63
    const int ak   = (tid & 3) * 4;     // 0,4,8,12

    float acc[8][8];
    #pragma unroll
    for (int i = 0; i < 8; i++)
        #pragma unroll
        for (int j = 0; j < 8; j++) acc[i][j] = 0.0f;

    for (int k0 = 0; k0 < HID; k0 += BK) {
        {
            int gr = bm0 + arow;
            float4 va = make_float4(0.f, 0.f, 0.f, 0.f);
            float4 vg = make_float4(0.f, 0.f, 0.f, 0.f);
            if (gr < n) {
                va = *reinterpret_cast<const float4*>(h   + (size_t)gr * HID + k0 + ak);
                vg = *reinterpret_cast<const float4*>(agg + (size_t)gr * HID + k0 + ak);
            }
            As[ak + 0][arow] = c1 * va.x + vg.x;
            As[ak + 1][arow] = c1 * va.y + vg.y;
            As[ak + 2][arow] = c1 * va.z + vg.z;
            As[ak + 3][arow] = c1 * va.w + vg.w;
        }
        #pragma unroll
        for (int p = 0; p < 4; p++) {
            int lin = tid + p * 256;
            int br  = lin >> 6;
            int bc  = (lin & 63) << 2;
            *reinterpret_cast<float4*>(&Bs[br][bc]) =
                *reinterpret_cast<const float4*>(W + (size_t)(k0 + br) * HID + bc);
        }
        __syncthreads();

        #pragma unroll
        for (int k = 0; k < BK; k++) {
            float a[8];
            #pragma unroll
            for (int i = 0; i < 8; i++) a[i] = As[k][ty * 8 + i];
            float4 b0 = *reinterpret_cast<float4*>(&Bs[k][tx * 4]);
            float4 b1 = *reinterpret_cast<float4*>(&Bs[k][128 + tx * 4]);
            float bb[8] = {b0.x, b0.y, b0.z, b0.w, b1.x, b1.y, b1.z, b1.w};
            #pragma unroll
            for (int i = 0; i < 8; i++)
                #pragma unroll
                for (int j = 0; j < 8; j++)
                    acc[i][j] = fmaf(a[i], bb[j], acc[i][j]);
        }
        __syncthreads();
    }

    float4 bv0 = *reinterpret_cast<const float4*>(b + tx * 4);
    float4 bv1 = *reinterpret_cast<const float4*>(b + 128 + tx * 4);
    float bias[8] = {bv0.x, bv0.y, bv0.z, bv0.w, bv1.x, bv1.y, bv1.z, bv1.w};

    #pragma unroll
    for (int i = 0; i < 8; i++) {
        int gr = bm0 + ty * 8 + i;
        if (gr >= n) continue;
        float4 o0, o1;
        o0.x = fmaxf(acc[i][0] + bias[0], 0.f);
        o0.y = fmaxf(acc[i][1] + bias[1], 0.f);
        o0.z = fmaxf(acc[i][2] + bias[2], 0.f);
        o0.w = fmaxf(acc[i][3] + bias[3], 0.f);
        o1.x = fmaxf(acc[i][4] + bias[4], 0.f);
        o1.y = fmaxf(acc[i][5] + bias[5], 0.f);
        o1.z = fmaxf(acc[i][6] + bias[6], 0.f);
        o1.w = fmaxf(acc[i][7] + bias[7], 0.f);
        *reinterpret_cast<float4*>(out + (size_t)gr * HID + tx * 4)       = o0;
        *reinterpret_cast<float4*>(out + (size_t)gr * HID + 128 + tx * 4) = o1;
    }
}

// ---------------------------------------------------------------------------
// GEMM2 (fused epilogue): out = relu( LN( t @ W2 + b2 + h_in ) * gamma + beta )
// Each warp owns 8 full rows -> LN via warp shuffles, zero extra HBM traffic.
// ---------------------------------------------------------------------------
__global__ __launch_bounds__(256) void gin_mlp2_kernel(
    const float* __restrict__ tin,
    const float* __restrict__ W,
    const float* __restrict__ b,
    const float* __restrict__ h_in,
    const float* __restrict__ gamma,
    const float* __restrict__ beta,
    float* __restrict__ out,
    int n)
{
    __shared__ float As[BK][BM + 1];
    __shared__ float Bs[BK][HID];

    const int tid = threadIdx.x;
    const int tx  = tid & 31;
    const int ty  = tid >> 5;
    const int bm0 = blockIdx.x * BM;

    const int arow = tid >> 2;
    const int ak   = (tid & 3) * 4;

    float acc[8][8];
    #pragma unroll
    for (int i = 0; i < 8; i++)
        #pragma unroll
        for (int j = 0; j < 8; j++) acc[i][j] = 0.0f;

    for (int k0 = 0; k0 < HID; k0 += BK) {
        {
            int gr = bm0 + arow;
            float4 va = make_float4(0.f, 0.f, 0.f, 0.f);
            if (gr < n)
                va = *reinterpret_cast<const float4*>(tin + (size_t)gr * HID + k0 + ak);
            As[ak + 0][arow] = va.x;
            As[ak + 1][arow] = va.y;
            As[ak + 2][arow] = va.z;
            As[ak + 3][arow] = va.w;
        }
        #pragma unroll
        for (int p = 0; p < 4; p++) {
            int lin = tid + p * 256;
            int br  = lin >> 6;
            int bc  = (lin & 63) << 2;
            *reinterpret_cast<float4*>(&Bs[br][bc]) =
                *reinterpret_cast<const float4*>(W + (size_t)(k0 + br) * HID + bc);
        }
        __syncthreads();

        #pragma unroll
        for (int k = 0; k < BK; k++) {
            float a[8];
            #pragma unroll
            for (int i = 0; i < 8; i++) a[i] = As[k][ty * 8 + i];
            float4 b0 = *reinterpret_cast<float4*>(&Bs[k][tx * 4]);
            float4 b1 = *reinterpret_cast<float4*>(&Bs[k][128 + tx * 4]);
            float bb[8] = {b0.x, b0.y, b0.z, b0.w, b1.x, b1.y, b1.z, b1.w};
            #pragma unroll
            for (int i = 0; i < 8; i++)
                #pragma unroll
                for (int j = 0; j < 8; j++)
                    acc[i][j] = fmaf(a[i], bb[j], acc[i][j]);
        }
        __syncthreads();
    }

    float4 bv0 = *reinterpret_cast<const float4*>(b + tx * 4);
    float4 bv1 = *reinterpret_cast<const float4*>(b + 128 + tx * 4);
    float bias[8] = {bv0.x, bv0.y, bv0.z, bv0.w, bv1.x, bv1.y, bv1.z, bv1.w};
    float4 gv0 = *reinterpret_cast<const float4*>(gamma + tx * 4);
    float4 gv1 = *reinterpret_cast<const float4*>(gamma + 128 + tx * 4);
    float gw[8] = {gv0.x, gv0.y, gv0.z, gv0.w, gv1.x, gv1.y, gv1.z, gv1.w};
    float4 pv0 = *reinterpret_cast<const float4*>(beta + tx * 4);
    float4 pv1 = *reinterpret_cast<const float4*>(beta + 128 + tx * 4);
    float bw[8] = {pv0.x, pv0.y, pv0.z, pv0.w, pv1.x, pv1.y, pv1.z, pv1.w};

    #pragma unroll
    for (int i = 0; i < 8; i++) {
        int gr = bm0 + ty * 8 + i;
        if (gr >= n) continue;   // uniform across the warp
        float4 r0 = *reinterpret_cast<const float4*>(h_in + (size_t)gr * HID + tx * 4);
        float4 r1 = *reinterpret_cast<const float4*>(h_in + (size_t)gr * HID + 128 + tx * 4);
        float x[8];
        x[0] = acc[i][0] + bias[0] + r0.x;
        x[1] = acc[i][1] + bias[1] + r0.y;
        x[2] = acc[i][2] + bias[2] + r0.z;
        x[3] = acc[i][3] + bias[3] + r0.w;
        x[4] = acc[i][4] + bias[4] + r1.x;
        x[5] = acc[i][5] + bias[5] + r1.y;
        x[6] = acc[i][6] + bias[6] + r1.z;
        x[7] = acc[i][7] + bias[7] + r1.w;

        float s = 0.f;
        #pragma unroll
        for (int j = 0; j < 8; j++) s += x[j];
        #pragma unroll
        for (int off = 16; off > 0; off >>= 1) s += __shfl_xor_sync(0xffffffffu, s, off);
        float mu = s * (1.0f / HID);

        float v = 0.f;
        #pragma unroll
        for (int j = 0; j < 8; j++) { float d = x[j] - mu; v = fmaf(d, d, v); }
        #pragma unroll
        for (int off = 16; off > 0; off >>= 1) v += __shfl_xor_sync(0xffffffffu, v, off);
        float rs = rsqrtf(v * (1.0f / HID) + LN_EPS);

        float4 o0, o1;
        o0.x = fmaxf((x[0] - mu) * rs * gw[0] + bw[0], 0.f);
        o0.y = fmaxf((x[1] - mu) * rs * gw[1] + bw[1], 0.f);
        o0.z = fmaxf((x[2] - mu) * rs * gw[2] + bw[2], 0.f);
        o0.w = fmaxf((x[3] - mu) * rs * gw[3] + bw[3], 0.f);
        o1.x = fmaxf((x[4] - mu) * rs * gw[4] + bw[4], 0.f);
        o1.y = fmaxf((x[5] - mu) * rs * gw[5] + bw[5], 0.f);
        o1.z = fmaxf((x[6] - mu) * rs * gw[6] + bw[6], 0.f);
        o1.w = fmaxf((x[7] - mu) * rs * gw[7] + bw[7], 0.f);
        *reinterpret_cast<float4*>(out + (size_t)gr * HID + tx * 4)       = o0;
        *reinterpret_cast<float4*>(out + (size_t)gr * HID + 128 + tx * 4) = o1;
    }
}

// ---------------------------------------------------------------------------
// Launch — inputs identified by element count (robust to ordering):
//   h: 25,600,000 | edge_index: 600,000 | W1,W2: 196,608 (in order)
//   eps: 3 | b1,b2,gamma,beta: 768 (in order)
// ---------------------------------------------------------------------------
extern "C" void kernel_launch(void* const* d_in, const int* in_sizes, int n_in,
                              void* d_out, int out_size)
{
    int idx_h = -1, idx_e = -1, idx_W1 = -1, idx_W2 = -1, idx_eps = -1;
    int idx768[4] = {-1, -1, -1, -1};
    int n768 = 0;
    for (int i = 0; i < n_in; i++) {
        int s = in_sizes[i];
        if      (s == NN * HID)            idx_h = i;
        else if (s == 2 * NE)              idx_e = i;
        else if (s == NLAYERS * HID * HID) { if (idx_W1 < 0) idx_W1 = i; else idx_W2 = i; }
        else if (s == NLAYERS)             idx_eps = i;
        else if (s == NLAYERS * HID && n768 < 4) idx768[n768++] = i;
    }

    const float* h_in0 = (const float*)d_in[idx_h];
    const void*  eidx  = d_in[idx_e];
    const float* W1    = (const float*)d_in[idx_W1];
    const float* W2    = (const float*)d_in[idx_W2];
    const float* eps   = (const float*)d_in[idx_eps];
    const float* b1    = (const float*)d_in[idx768[0]];
    const float* b2    = (const float*)d_in[idx768[1]];
    const float* gamma = (const float*)d_in[idx768[2]];
    const float* beta  = (const float*)d_in[idx768[3]];
    float*       out   = (float*)d_out;

    float *agg, *t, *h1, *h2;
    cudaGetSymbolAddress((void**)&agg, g_agg);
    cudaGetSymbolAddress((void**)&t,   g_t);
    cudaGetSymbolAddress((void**)&h1,  g_h1);
    cudaGetSymbolAddress((void**)&h2,  g_h2);

    const int n_blocks_gemm    = (NN + BM - 1) / BM;
    const int n_blocks_scatter = (NE + 3) / 4;

    const float* cur = h_in0;
    float* outs[NLAYERS] = {h1, h2, out};

    for (int l = 0; l < NLAYERS; l++) {
        cudaMemsetAsync(agg, 0, (size_t)NN * HID * sizeof(float), 0);
        scatter_add_kernel<<<n_blocks_scatter, 256>>>(cur, eidx, agg, NE);
        gin_mlp1_kernel<<<n_blocks_gemm, 256>>>(
            cur, agg, W1 + (size_t)l * HID * HID, b1 + l * HID, eps, l, t, NN);
        gin_mlp2_kernel<<<n_blocks_gemm, 256>>>(
            t, W2 + (size_t)l * HID * HID, b2 + l * HID, cur,
            gamma + l * HID, beta + l * HID, outs[l], NN);
        cur = outs[l];
    }
}

// round 3
// speedup vs baseline: 1.8463x; 1.8463x over previous
#include <cuda_runtime.h>
#include <cuda_bf16.h>
#include <cstdint>

#define NN      100000
#define NE      300000
#define HID     256
#define NLAYERS 3
#define BM      64
#define LN_EPS  1e-5f

// Scratch (static device arrays — allocation-guard-safe)
__device__ float g_agg[NN * HID];
__device__ float g_t  [NN * HID];
__device__ float g_h1 [NN * HID];
__device__ float g_h2 [NN * HID];

// ---------------------------------------------------------------------------
// Helpers
// ---------------------------------------------------------------------------
__device__ __forceinline__ uint32_t f2tf(float x) {
    uint32_t r;
    asm("cvt.rna.tf32.f32 %0, %1;" : "=r"(r) : "f"(x));
    return r;
}

__device__ __forceinline__ void mma_tf32(float* c, const uint32_t* a, const uint32_t* b) {
    asm volatile(
        "mma.sync.aligned.m16n8k8.row.col.f32.tf32.tf32.f32 "
        "{%0,%1,%2,%3}, {%4,%5,%6,%7}, {%8,%9}, {%0,%1,%2,%3};"
        : "+f"(c[0]), "+f"(c[1]), "+f"(c[2]), "+f"(c[3])
        : "r"(a[0]), "r"(a[1]), "r"(a[2]), "r"(a[3]), "r"(b[0]), "r"(b[1]));
}

// ---------------------------------------------------------------------------
// Edge scatter: agg[dst] += h[src].  64 threads per edge, float4 vector atomic.
// edge_index dtype (int32 vs int64) detected in-kernel.
// ---------------------------------------------------------------------------
__global__ __launch_bounds__(256) void scatter_add_kernel(
    const float* __restrict__ h,
    const void* __restrict__ edge_raw,
    float* __restrict__ agg,
    int n_edges)
{
    int e  = blockIdx.x * 4 + (threadIdx.x >> 6);
    int t  = threadIdx.x & 63;
    if (e >= n_edges) return;

    const int* e32 = (const int*)edge_raw;
    bool is64 = (e32[1] == 0) & (e32[3] == 0) & (e32[5] == 0) & (e32[7] == 0);

    long long s, d;
    if (is64) {
        const long long* e64 = (const long long*)edge_raw;
        s = e64[e];
        d = e64[n_edges + e];
    } else {
        s = e32[e];
        d = e32[n_edges + e];
    }

    float4 v = *reinterpret_cast<const float4*>(h + (size_t)s * HID + t * 4);
    float* o = agg + (size_t)d * HID + t * 4;
#if __CUDA_ARCH__ >= 900
    atomicAdd(reinterpret_cast<float4*>(o), v);
#else
    atomicAdd(o + 0, v.x); atomicAdd(o + 1, v.y);
    atomicAdd(o + 2, v.z); atomicAdd(o + 3, v.w);
#endif
}

// ---------------------------------------------------------------------------
// tf32 tensor-core GEMM, 64x256 block tile, BK=32, 8 warps (2m x 4n),
// warp tile 32x64 via m16n8k8 mma (2 m-tiles x 8 n-tiles).
// IS1: A = (1+eps)*h + agg, epilogue relu(+b1)       -> out
// !IS1: A = t,              epilogue LN(acc+b2+h)... -> out
// ---------------------------------------------------------------------------
template<bool IS1>
__global__ __launch_bounds__(256) void gin_gemm_kernel(
    const float* __restrict__ Ain,     // h (IS1) or t (!IS1)
    const float* __restrict__ agg,     // IS1 only
    const float* __restrict__ W,
    const float* __restrict__ bvec,
    const float* __restrict__ eps,
    int layer,
    const float* __restrict__ resid,   // !IS1 only
    const float* __restrict__ gamma,
    const float* __restrict__ beta,
    float* __restrict__ out,
    int n)
{
    __shared__ uint32_t As[BM][36];     //  9216 B, bank-conflict-free frag reads
    __shared__ uint32_t Bs[32][264];    // 33792 B

    const int tid  = threadIdx.x;
    const int lane = tid & 31;
    const int warp = tid >> 5;
    const int g    = lane >> 2;        // 0..7
    const int tg   = lane & 3;         // 0..3
    const int wm   = warp >> 2;        // 0..1  (m)
    const int wn   = warp & 3;         // 0..3  (n)
    const int bm0  = blockIdx.x * BM;

    float c1 = 0.0f;
    if (IS1) c1 = 1.0f + eps[layer];

    float acc[2][8][4];
    #pragma unroll
    for (int mt = 0; mt < 2; mt++)
        #pragma unroll
        for (int nt = 0; nt < 8; nt++)
            #pragma unroll
            for (int r = 0; r < 4; r++) acc[mt][nt][r] = 0.0f;

    for (int k0 = 0; k0 < HID; k0 += 32) {
        // ---- A tile: 64 x 32, fused producer ----
        #pragma unroll
        for (int p = 0; p < 2; p++) {
            int f  = tid + p * 256;        // float4 index
            int m  = f >> 3;
            int kq = (f & 7) << 2;
            int gr = bm0 + m;
            float4 v = make_float4(0.f, 0.f, 0.f, 0.f);
            if (gr < n) {
                if (IS1) {
                    float4 vh = *reinterpret_cast<const float4*>(Ain + (size_t)gr * HID + k0 + kq);
                    float4 vg = *reinterpret_cast<const float4*>(agg + (size_t)gr * HID + k0 + kq);
                    v.x = fmaf(c1, vh.x, vg.x); v.y = fmaf(c1, vh.y, vg.y);
                    v.z = fmaf(c1, vh.z, vg.z); v.w = fmaf(c1, vh.w, vg.w);
                } else {
                    v = *reinterpret_cast<const float4*>(Ain + (size_t)gr * HID + k0 + kq);
                }
            }
            uint4 u = make_uint4(f2tf(v.x), f2tf(v.y), f2tf(v.z), f2tf(v.w));
            *reinterpret_cast<uint4*>(&As[m][kq]) = u;
        }
        // ---- B tile: 32 x 256 from W (k-major, direct copy) ----
        #pragma unroll
        for (int p = 0; p < 8; p++) {
            int f  = tid + p * 256;
            int k  = f >> 6;
            int nq = (f & 63) << 2;
            float4 v = *reinterpret_cast<const float4*>(W + (size_t)(k0 + k) * HID + nq);
            uint4 u = make_uint4(f2tf(v.x), f2tf(v.y), f2tf(v.z), f2tf(v.w));
            *reinterpret_cast<uint4*>(&Bs[k][nq]) = u;
        }
        __syncthreads();

        #pragma unroll
        for (int s = 0; s < 4; s++) {
            int ks = s * 8;
            uint32_t a[2][4];
            #pragma unroll
            for (int mt = 0; mt < 2; mt++) {
                int row = wm * 32 + mt * 16 + g;
                a[mt][0] = As[row    ][ks + tg];
                a[mt][1] = As[row + 8][ks + tg];
                a[mt][2] = As[row    ][ks + tg + 4];
                a[mt][3] = As[row + 8][ks + tg + 4];
            }
            uint32_t bf[8][2];
            #pragma unroll
            for (int nt = 0; nt < 8; nt++) {
                int nc = wn * 64 + nt * 8 + g;
                bf[nt][0] = Bs[ks + tg    ][nc];
                bf[nt][1] = Bs[ks + tg + 4][nc];
            }
            #pragma unroll
            for (int mt = 0; mt < 2; mt++)
                #pragma unroll
                for (int nt = 0; nt < 8; nt++)
                    mma_tf32(acc[mt][nt], a[mt], bf[nt]);
        }
        __syncthreads();
    }

    // Thread covers rows {wm*32 + mt*16 + h8*8 + g}, cols {wn*64 + nt*8 + 2*tg + c}
    // acc[mt][nt][2*h8 + c]

    float bias[8][2];
    #pragma unroll
    for (int nt = 0; nt < 8; nt++) {
        float2 bv = *reinterpret_cast<const float2*>(bvec + wn * 64 + nt * 8 + 2 * tg);
        bias[nt][0] = bv.x; bias[nt][1] = bv.y;
    }

    if (IS1) {
        #pragma unroll
        for (int mt = 0; mt < 2; mt++)
            #pragma unroll
            for (int h8 = 0; h8 < 2; h8++) {
                int row = bm0 + wm * 32 + mt * 16 + h8 * 8 + g;
                if (row >= n) continue;
                #pragma unroll
                for (int nt = 0; nt < 8; nt++) {
                    float2 o;
                    o.x = fmaxf(acc[mt][nt][2 * h8 + 0] + bias[nt][0], 0.f);
                    o.y = fmaxf(acc[mt][nt][2 * h8 + 1] + bias[nt][1], 0.f);
                    *reinterpret_cast<float2*>(out + (size_t)row * HID + wn * 64 + nt * 8 + 2 * tg) = o;
                }
            }
    } else {
        // x = acc + bias + residual (accumulate in place)
        #pragma unroll
        for (int mt = 0; mt < 2; mt++)
            #pragma unroll
            for (int h8 = 0; h8 < 2; h8++) {
                int row = bm0 + wm * 32 + mt * 16 + h8 * 8 + g;
                bool valid = row < n;
                #pragma unroll
                for (int nt = 0; nt < 8; nt++) {
                    float2 r = make_float2(0.f, 0.f);
                    if (valid)
                        r = *reinterpret_cast<const float2*>(resid + (size_t)row * HID + wn * 64 + nt * 8 + 2 * tg);
                    acc[mt][nt][2 * h8 + 0] += bias[nt][0] + r.x;
                    acc[mt][nt][2 * h8 + 1] += bias[nt][1] + r.y;
                }
            }

        // per-row partial sums over this warp's 64-col slice
        float ss[2][2], qq[2][2];
        #pragma unroll
        for (int mt = 0; mt < 2; mt++)
            #pragma unroll
            for (int h8 = 0; h8 < 2; h8++) {
                float s = 0.f, q = 0.f;
                #pragma unroll
                for (int nt = 0; nt < 8; nt++) {
                    float x0 = acc[mt][nt][2 * h8 + 0];
                    float x1 = acc[mt][nt][2 * h8 + 1];
                    s += x0 + x1;
                    q = fmaf(x0, x0, q); q = fmaf(x1, x1, q);
                }
                // reduce across the 4 lanes sharing this row (tg = 0..3)
                #pragma unroll
                for (int off = 1; off <= 2; off <<= 1) {
                    s += __shfl_xor_sync(0xffffffffu, s, off);
                    q += __shfl_xor_sync(0xffffffffu, q, off);
                }
                ss[mt][h8] = s; qq[mt][h8] = q;
            }

        // cross-warp (4 n-warps) reduction via smem (Bs reused; loop ended with sync)
        float* smsum = reinterpret_cast<float*>(&Bs[0][0]);       // [4][64]
        float* smsq  = smsum + 4 * 64;                            // [4][64]
        if (tg == 0) {
            #pragma unroll
            for (int mt = 0; mt < 2; mt++)
                #pragma unroll
                for (int h8 = 0; h8 < 2; h8++) {
                    int rowl = wm * 32 + mt * 16 + h8 * 8 + g;
                    smsum[wn * 64 + rowl] = ss[mt][h8];
                    smsq [wn * 64 + rowl] = qq[mt][h8];
                }
        }
        __syncthreads();

        float mu[2][2], rs[2][2];
        #pragma unroll
        for (int mt = 0; mt < 2; mt++)
            #pragma unroll
            for (int h8 = 0; h8 < 2; h8++) {
                int rowl = wm * 32 + mt * 16 + h8 * 8 + g;
                float S = 0.f, Q = 0.f;
                #pragma unroll
                for (int w = 0; w < 4; w++) {
                    S += smsum[w * 64 + rowl];
                    Q += smsq [w * 64 + rowl];
                }
                float m = S * (1.0f / HID);
                float v = Q * (1.0f / HID) - m * m;
                mu[mt][h8] = m;
                rs[mt][h8] = rsqrtf(v + LN_EPS);
            }

        float gm[8][2], bt[8][2];
        #pragma unroll
        for (int nt = 0; nt < 8; nt++) {
            float2 gv = *reinterpret_cast<const float2*>(gamma + wn * 64 + nt * 8 + 2 * tg);
            float2 pv = *reinterpret_cast<const float2*>(beta  + wn * 64 + nt * 8 + 2 * tg);
            gm[nt][0] = gv.x; gm[nt][1] = gv.y;
            bt[nt][0] = pv.x; bt[nt][1] = pv.y;
        }

        #pragma unroll
        for (int mt = 0; mt < 2; mt++)
            #pragma unroll
            for (int h8 = 0; h8 < 2; h8++) {
                int row = bm0 + wm * 32 + mt * 16 + h8 * 8 + g;
                if (row >= n) continue;
                float m = mu[mt][h8], r = rs[mt][h8];
                #pragma unroll
                for (int nt = 0; nt < 8; nt++) {
                    float2 o;
                    o.x = fmaxf((acc[mt][nt][2 * h8 + 0] - m) * r * gm[nt][0] + bt[nt][0], 0.f);
                    o.y = fmaxf((acc[mt][nt][2 * h8 + 1] - m) * r * gm[nt][1] + bt[nt][1], 0.f);
                    *reinterpret_cast<float2*>(out + (size_t)row * HID + wn * 64 + nt * 8 + 2 * tg) = o;
                }
            }
    }
}

// ---------------------------------------------------------------------------
// Launch — inputs identified by element count (robust to ordering)
// ---------------------------------------------------------------------------
extern "C" void kernel_launch(void* const* d_in, const int* in_sizes, int n_in,
                              void* d_out, int out_size)
{
    int idx_h = -1, idx_e = -1, idx_W1 = -1, idx_W2 = -1, idx_eps = -1;
    int idx768[4] = {-1, -1, -1, -1};
    int n768 = 0;
    for (int i = 0; i < n_in; i++) {
        int s = in_sizes[i];
        if      (s == NN * HID)            idx_h = i;
        else if (s == 2 * NE)              idx_e = i;
        else if (s == NLAYERS * HID * HID) { if (idx_W1 < 0) idx_W1 = i; else idx_W2 = i; }
        else if (s == NLAYERS)             idx_eps = i;
        else if (s == NLAYERS * HID && n768 < 4) idx768[n768++] = i;
    }

    const float* h_in0 = (const float*)d_in[idx_h];
    const void*  eidx  = d_in[idx_e];
    const float* W1    = (const float*)d_in[idx_W1];
    const float* W2    = (const float*)d_in[idx_W2];
    const float* eps   = (const float*)d_in[idx_eps];
    const float* b1    = (const float*)d_in[idx768[0]];
    const float* b2    = (const float*)d_in[idx768[1]];
    const float* gamma = (const float*)d_in[idx768[2]];
    const float* beta  = (const float*)d_in[idx768[3]];
    float*       out   = (float*)d_out;

    float *agg, *t, *h1, *h2;
    cudaGetSymbolAddress((void**)&agg, g_agg);
    cudaGetSymbolAddress((void**)&t,   g_t);
    cudaGetSymbolAddress((void**)&h1,  g_h1);
    cudaGetSymbolAddress((void**)&h2,  g_h2);

    const int n_blocks_gemm    = (NN + BM - 1) / BM;
    const int n_blocks_scatter = (NE + 3) / 4;

    const float* cur = h_in0;
    float* outs[NLAYERS] = {h1, h2, out};

    for (int l = 0; l < NLAYERS; l++) {
        cudaMemsetAsync(agg, 0, (size_t)NN * HID * sizeof(float), 0);
        scatter_add_kernel<<<n_blocks_scatter, 256>>>(cur, eidx, agg, NE);
        gin_gemm_kernel<true><<<n_blocks_gemm, 256>>>(
            cur, agg, W1 + (size_t)l * HID * HID, b1 + l * HID, eps, l,
            nullptr, nullptr, nullptr, t, NN);
        gin_gemm_kernel<false><<<n_blocks_gemm, 256>>>(
            t, nullptr, W2 + (size_t)l * HID * HID, b2 + l * HID, eps, l,
            cur, gamma + l * HID, beta + l * HID, outs[l], NN);
        cur = outs[l];
    }
}